// round 9
// baseline (speedup 1.0000x reference)
#include <cuda_runtime.h>
#include <cstdint>

// Water constraint residuals:
//   x: [B=16, N=200000, D=18] fp32  (first 9 floats/row = 3 particles x xyz)
//   l: [3] fp32; out: [B, N, 3] fp32 = |r0-r1|-l0, |r1-r2|-l1, |r2-r0|-l2
//
// Per 4-row group (288B) all needed bytes are [0,256) = 16 float4s.
// Block of 256 threads handles 64 groups (256 rows):
//   1. cp.async.cg stages 1024 float4s coalesced (4 LDGSTS.128/thread,
//      no register round-trip, L1 bypass). Same 8-of-9 sector DRAM footprint.
//   2. Rows read from smem as 4x LDS.64 + 1x LDS.32 (base word 68g+18r is
//      always even).
//   3. Results staged back into smem, stored as 192 coalesced STG.128.

#define GROUPS_PER_BLOCK 64
#define SMEM_GROUP_F4    17                     // 16 data + 1 pad
#define SMEM_GROUP_F     (SMEM_GROUP_F4 * 4)    // 68 words

__global__ __launch_bounds__(256) void water_kernel4(
    const float4* __restrict__ x4,
    const float* __restrict__ l,
    float4* __restrict__ out4)
{
    __shared__ float4 sm4[GROUPS_PER_BLOCK * SMEM_GROUP_F4];
    float* sm = reinterpret_cast<float*>(sm4);

    const int tid = threadIdx.x;
    const long long g_base = (long long)blockIdx.x * GROUPS_PER_BLOCK;

    // ---- Stage via cp.async (bypass L1, no reg round-trip) ----
    uint32_t s_addr = (uint32_t)__cvta_generic_to_shared(sm4);
    #pragma unroll
    for (int i = 0; i < 4; i++) {
        int L = tid + 256 * i;
        int gl = L >> 4;           // local group 0..63
        int j  = L & 15;           // float4 within group
        const float4* src = x4 + (g_base + gl) * 18 + j;
        uint32_t dst = s_addr + (uint32_t)(gl * SMEM_GROUP_F4 + j) * 16;
        asm volatile("cp.async.cg.shared.global [%0], [%1], 16;"
                     :: "r"(dst), "l"(src));
    }
    asm volatile("cp.async.commit_group;");

    const float l0 = __ldg(l + 0);
    const float l1 = __ldg(l + 1);
    const float l2 = __ldg(l + 2);

    asm volatile("cp.async.wait_group 0;");
    __syncthreads();

    // ---- Compute: thread t -> row (t&3) of local group (t>>2) ----
    const int base = (tid >> 2) * SMEM_GROUP_F + (tid & 3) * 18;  // even
    const float2* s2 = reinterpret_cast<const float2*>(sm + base);
    float2 p01 = s2[0];            // f0 f1
    float2 p23 = s2[1];            // f2 f3
    float2 p45 = s2[2];            // f4 f5
    float2 p67 = s2[3];            // f6 f7
    float  f8  = sm[base + 8];

    // r0=(f0,f1,f2) r1=(f3,f4,f5) r2=(f6,f7,f8)
    float d0x = p01.x - p23.y;     // r0 - r1
    float d0y = p01.y - p45.x;
    float d0z = p23.x - p45.y;
    float d1x = p23.y - p67.x;     // r1 - r2
    float d1y = p45.x - p67.y;
    float d1z = p45.y - f8;
    float d2x = p67.x - p01.x;     // r2 - r0
    float d2y = p67.y - p01.y;
    float d2z = f8   - p23.x;

    float n0 = sqrtf(fmaf(d0x, d0x, fmaf(d0y, d0y, d0z * d0z)));
    float n1 = sqrtf(fmaf(d1x, d1x, fmaf(d1y, d1y, d1z * d1z)));
    float n2 = sqrtf(fmaf(d2x, d2x, fmaf(d2y, d2y, d2z * d2z)));

    // ---- Coalesced output: stage 768 floats, store 192 float4 ----
    __syncthreads();               // all smem reads complete before reuse
    sm[tid * 3 + 0] = n0 - l0;     // 3t mod 32 distinct per warp: conflict-free
    sm[tid * 3 + 1] = n1 - l1;
    sm[tid * 3 + 2] = n2 - l2;
    __syncthreads();

    if (tid < 192) {
        float4 v = reinterpret_cast<const float4*>(sm)[tid];
        __stcs(out4 + (long long)blockIdx.x * 192 + tid, v);
    }
}

extern "C" void kernel_launch(void* const* d_in, const int* in_sizes, int n_in,
                              void* d_out, int out_size)
{
    const float4* x4 = (const float4*)d_in[0];
    const float* l = (const float*)d_in[1];
    float4* out4 = (float4*)d_out;

    int M = in_sizes[0] / 18;      // 3,200,000 rows (divisible by 256)
    int grid = M / 256;            // 12500 blocks

    water_kernel4<<<grid, 256>>>(x4, l, out4);
}